// round 15
// baseline (speedup 1.0000x reference)
#include <cuda_runtime.h>
#include <cuda_bf16.h>
#include <math.h>
#include <stdint.h>

// ---------------- problem constants ----------------
#define B_   2
#define L_   128
#define LY_  16
#define E_   256
#define V_   32000
#define C_   18        // 2 static + LY dynamic mixture components

// Distinct candidate rows: 0..255 emit(b,l), 256..511 z(b,l), 512..543 y(b,j)
#define R_      544
#define RPAD    640    // 5 tiles of 128
#define BM      128
#define NMT     5      // RPAD/BM
#define NVT     250    // V_/128
#define NVT_PAD 256

#define TILE_BYTES  65536     // one 128-row x 256-k bf16 tile (blocked SW128)
#define CHUNK_BYTES 16384     // one k64 chunk (128 rows x 128B)
// k_main: 1023 slack + 1024 ctrl + A + B0 + B1 + pss(4K)
#define SMEM_REQ    202752
// k_sgemm: 1023 slack + A + B0 + B1
#define SG_SMEM     197632

// k_conv block layout (no static smem -> full occupancy)
#define NCONV4 4000           // embed conversion blocks (1 unit/thread)
#define NCAND  48             // cand rows 256..639 copy blocks
#define CONV_BLOCKS (NCONV4 + NCAND + 2)

// ---------------- device scratch (no allocation allowed) ----------------
__device__ float    g_cand[RPAD * E_];
__device__ float    g_xkey[B_ * C_ * E_];
__device__ float    g_partial[RPAD * NVT_PAD];
__device__ float    g_negcent[B_ * L_];
__device__ int      g_yt64;
__device__ int      g_blkdone;                              // k_final finish counter
__device__ uint32_t g_candb[NMT * TILE_BYTES / 4];          // cand bf16, swizzled
__device__ uint32_t g_ebf[(size_t)NVT * TILE_BYTES / 4];    // embed bf16, swizzled

// ---------------- PTX helpers (plain sm_100-safe) ----------
__device__ __forceinline__ uint32_t smem_u32(const void* p) {
    uint32_t a;
    asm("{ .reg .u64 t; cvta.to.shared.u64 t, %1; cvt.u32.u64 %0, t; }"
        : "=r"(a) : "l"(p));
    return a;
}
#define MBARRIER_INIT(mb, cnt) \
    asm volatile("mbarrier.init.shared.b64 [%0], %1;" :: "r"(mb), "r"((uint32_t)(cnt)) : "memory")
#define MBARRIER_EXPECT_TX(mb, bytes) \
    asm volatile("mbarrier.arrive.expect_tx.shared.b64 _, [%0], %1;" \
                 :: "r"(mb), "r"((uint32_t)(bytes)) : "memory")
#define MBARRIER_WAIT(mb, ph) do {                                              \
    uint32_t _mb = (mb), _ph = (ph), _done;                                     \
    asm volatile("{\n\t.reg .pred p;\n\t"                                       \
        "mbarrier.try_wait.parity.acquire.cta.shared::cta.b64 p, [%1], %2;\n\t" \
        "selp.b32 %0, 1, 0, p;\n\t}" : "=r"(_done) : "r"(_mb), "r"(_ph) : "memory"); \
    if (!_done) {                                                               \
        asm volatile("{\n\t.reg .pred P1;\n\t"                                  \
            "WL_%=:\n\t"                                                        \
            "mbarrier.try_wait.parity.acquire.cta.shared::cta.b64 P1, [%0], %1, 0x989680;\n\t" \
            "@P1 bra.uni WD_%=;\n\t"                                            \
            "bra.uni WL_%=;\n\t"                                                \
            "WD_%=:\n\t}" :: "r"(_mb), "r"(_ph) : "memory");                    \
    }                                                                           \
} while (0)
#define CP_ASYNC_BULK(dst, src, bytes, mb) \
    asm volatile("cp.async.bulk.shared::cluster.global.mbarrier::complete_tx::bytes " \
                 "[%0], [%1], %2, [%3];" \
                 :: "r"(dst), "l"(src), "r"((uint32_t)(bytes)), "r"(mb) : "memory")

#define LDSM_X4(r, addr) \
    asm volatile("ldmatrix.sync.aligned.m8n8.x4.shared.b16 {%0,%1,%2,%3}, [%4];" \
        : "=r"((r)[0]), "=r"((r)[1]), "=r"((r)[2]), "=r"((r)[3]) : "r"(addr))

#define MMA_BF16(c, a, b0, b1) \
    asm volatile("mma.sync.aligned.m16n8k16.row.col.f32.bf16.bf16.f32 " \
        "{%0,%1,%2,%3}, {%4,%5,%6,%7}, {%8,%9}, {%0,%1,%2,%3};" \
        : "+f"((c)[0]), "+f"((c)[1]), "+f"((c)[2]), "+f"((c)[3]) \
        : "r"((a)[0]), "r"((a)[1]), "r"((a)[2]), "r"((a)[3]), "r"(b0), "r"(b1))

// pack two fp32 -> bf16x2 word (lo = element k, hi = element k+1), 1 instr
#define CVTPACK(d, lo, hi) \
    asm("cvt.rn.bf16x2.f32 %0, %1, %2;" : "=r"(d) : "f"(hi), "f"(lo))

__device__ __forceinline__ uint32_t pack_bf16(float a, float b) {
    __nv_bfloat162 t(__float2bfloat16_rn(a), __float2bfloat16_rn(b));
    return *reinterpret_cast<uint32_t*>(&t);
}
// swizzled byte offset of the 16B unit holding pairs [q0, q0+4), q0 % 4 == 0
__device__ __forceinline__ size_t sw_unit(int tile, int r, int q0) {
    int c = q0 >> 5;
    int boff = r * 128 + 4 * (q0 & 31);
    int sw = boff ^ ((boff >> 3) & 0x70);
    return (size_t)tile * TILE_BYTES + (size_t)c * CHUNK_BYTES + sw;
}
// swizzled 4B-word index of pair q
__device__ __forceinline__ size_t sw_pair(int tile, int r, int q) {
    int c = q >> 5;
    int boff = r * 128 + 4 * (q & 31);
    int sw = boff ^ ((boff >> 3) & 0x70);
    return ((size_t)tile * TILE_BYTES + (size_t)c * CHUNK_BYTES + sw) >> 2;
}

// Fragment loader for one k16 step (software pipeline unit)
__device__ __forceinline__ void load_frags(
    uint32_t Abase, uint32_t B0, uint32_t B1, int s,
    int a_row0, int a_kd, int b_row0, int b_kd,
    uint32_t (&a)[4][4], uint32_t (&f0)[2][4], uint32_t (&f1)[2][4]) {
    const uint32_t Ac = Abase + (s >> 2) * CHUNK_BYTES;
    const uint32_t Bc0 = B0 + (s >> 2) * CHUNK_BYTES;
    const uint32_t Bc1 = B1 + (s >> 2) * CHUNK_BYTES;
    const int kg = (s & 3) * 2;
#pragma unroll
    for (int mi = 0; mi < 4; ++mi) {
        int r = a_row0 + mi * 16;
        LDSM_X4(a[mi], Ac + r * 128 + (((kg + a_kd) ^ (r & 7)) << 4));
    }
#pragma unroll
    for (int p = 0; p < 2; ++p) {
        int r = b_row0 + p * 16;
        uint32_t off = r * 128 + (((kg + b_kd) ^ (r & 7)) << 4);
        LDSM_X4(f0[p], Bc0 + off);
        LDSM_X4(f1[p], Bc1 + off);
    }
}

// ---------------------------------------------------------------------------
// k_sgemm: 3 CTAs on tensor cores.
//   bx 0/1: emit rows [bx*128, bx*128+128) = xsa @ Wemit^T + bemit
//   bx 2  : dyn keys = y @ Wdyn^T + bdyn  (A rows >= 32 are don't-care)
// Each CTA converts its A (128 rows) and B (256 rows) fp32 -> bf16 SW128
// into smem, runs the proven frag-pipelined 16-step MMA loop, then writes
// fp32(+bias) results and (for emit) the bf16-swizzled g_candb tiles.
// ---------------------------------------------------------------------------
__global__ void __launch_bounds__(256, 1) k_sgemm(const float* __restrict__ xsa,
                                                  const float* __restrict__ y,
                                                  const float* __restrict__ Wemit,
                                                  const float* __restrict__ Wdyn,
                                                  const float* __restrict__ bemit,
                                                  const float* __restrict__ bdyn) {
    extern __shared__ __align__(16) char smem_raw[];
    uint32_t sb = smem_u32(smem_raw);
    uint32_t ab = (sb + 1023u) & ~1023u;
    uint32_t Abase = ab;
    uint32_t B0 = Abase + TILE_BYTES;
    uint32_t B1 = B0 + TILE_BYTES;

    const int tid = threadIdx.x;
    const int lane = tid & 31, wid = tid >> 5;
    const int wm = wid & 1, wn = wid >> 1;
    const int bx = blockIdx.x;

    const float* Asrc = (bx < 2) ? (xsa + (size_t)bx * 128 * E_) : y;
    const float* Bsrc = (bx < 2) ? Wemit : Wdyn;
    const float* bias = (bx < 2) ? bemit : bdyn;

    // ---- Convert operands fp32 -> bf16 SW128 into smem ----
    {
        int r = tid >> 1;                    // row 0..127
        int tb = (tid & 1) * 4;              // unit offset within 8-unit group
        // A tile (dyn: clamp to 32 valid rows)
        int ra = (bx == 2) ? (r & 31) : r;
        const float4* av = reinterpret_cast<const float4*>(Asrc + (size_t)ra * E_);
        char* adst = smem_raw + (Abase - sb);
#pragma unroll
        for (int c = 0; c < 4; ++c)
#pragma unroll
            for (int i = 0; i < 4; ++i) {
                int t = 8 * c + tb + i;
                float4 a = av[t * 2], b2 = av[t * 2 + 1];
                uint4 w;
                CVTPACK(w.x, a.x, a.y);
                CVTPACK(w.y, a.z, a.w);
                CVTPACK(w.z, b2.x, b2.y);
                CVTPACK(w.w, b2.z, b2.w);
                int off = c * CHUNK_BYTES + r * 128 + (((t & 7) ^ (r & 7)) << 4);
                *reinterpret_cast<uint4*>(adst + off) = w;
            }
        // B tiles (rows 0..127 -> B0, 128..255 -> B1)
#pragma unroll
        for (int h = 0; h < 2; ++h) {
            const float4* bv = reinterpret_cast<const float4*>(Bsrc + (size_t)(h * 128 + r) * E_);
            char* bdst = smem_raw + ((h ? B1 : B0) - sb);
#pragma unroll
            for (int c = 0; c < 4; ++c)
#pragma unroll
                for (int i = 0; i < 4; ++i) {
                    int t = 8 * c + tb + i;
                    float4 a = bv[t * 2], b2 = bv[t * 2 + 1];
                    uint4 w;
                    CVTPACK(w.x, a.x, a.y);
                    CVTPACK(w.y, a.z, a.w);
                    CVTPACK(w.z, b2.x, b2.y);
                    CVTPACK(w.w, b2.z, b2.w);
                    int off = c * CHUNK_BYTES + r * 128 + (((t & 7) ^ (r & 7)) << 4);
                    *reinterpret_cast<uint4*>(bdst + off) = w;
                }
        }
    }
    __syncthreads();

    // ldmatrix lane address parameters
    const int q = lane >> 3, j = lane & 7;
    const int a_row0 = wm * 64 + ((q & 1) << 3) + j;
    const int a_kd = q >> 1;
    const int b_row0 = wn * 32 + ((q & 2) << 2) + j;
    const int b_kd = q & 1;
    const int g = lane >> 2, t4 = lane & 3;

    float c[2][4][4][4];
#pragma unroll
    for (int h = 0; h < 2; ++h)
#pragma unroll
        for (int mi = 0; mi < 4; ++mi)
#pragma unroll
            for (int nj = 0; nj < 4; ++nj)
#pragma unroll
                for (int e = 0; e < 4; ++e) c[h][mi][nj][e] = 0.f;

    uint32_t afr[2][4][4], bf0[2][2][4], bf1[2][2][4];
    load_frags(Abase, B0, B1, 0, a_row0, a_kd, b_row0, b_kd,
               afr[0], bf0[0], bf1[0]);
#pragma unroll
    for (int s = 0; s < 16; ++s) {
        const int cur = s & 1, nxt = cur ^ 1;
        if (s < 15)
            load_frags(Abase, B0, B1, s + 1, a_row0, a_kd, b_row0, b_kd,
                       afr[nxt], bf0[nxt], bf1[nxt]);
#pragma unroll
        for (int mi = 0; mi < 4; ++mi)
#pragma unroll
            for (int p = 0; p < 2; ++p) {
                MMA_BF16(c[0][mi][2 * p],     afr[cur][mi], bf0[cur][p][0], bf0[cur][p][1]);
                MMA_BF16(c[0][mi][2 * p + 1], afr[cur][mi], bf0[cur][p][2], bf0[cur][p][3]);
                MMA_BF16(c[1][mi][2 * p],     afr[cur][mi], bf1[cur][p][0], bf1[cur][p][1]);
                MMA_BF16(c[1][mi][2 * p + 1], afr[cur][mi], bf1[cur][p][2], bf1[cur][p][3]);
            }
    }

    // ---- Epilogue: bias add + fp32 store (+ bf16 swizzled for emit) ----
#pragma unroll
    for (int h = 0; h < 2; ++h)
#pragma unroll
        for (int mi = 0; mi < 4; ++mi)
#pragma unroll
            for (int nj = 0; nj < 4; ++nj) {
                int col0 = h * 128 + wn * 32 + nj * 8 + 2 * t4;
                float b0v = bias[col0], b1v = bias[col0 + 1];
                float v00 = c[h][mi][nj][0] + b0v;   // row r0,   col0
                float v01 = c[h][mi][nj][1] + b1v;   // row r0,   col0+1
                float v10 = c[h][mi][nj][2] + b0v;   // row r0+8, col0
                float v11 = c[h][mi][nj][3] + b1v;   // row r0+8, col0+1
                int r0 = wm * 64 + mi * 16 + g;
                if (bx < 2) {
                    int row0 = bx * 128 + r0;
                    g_cand[(size_t)row0 * E_ + col0] = v00;
                    g_cand[(size_t)row0 * E_ + col0 + 1] = v01;
                    g_cand[(size_t)(row0 + 8) * E_ + col0] = v10;
                    g_cand[(size_t)(row0 + 8) * E_ + col0 + 1] = v11;
                    int qp = col0 >> 1;
                    g_candb[sw_pair(bx, r0, qp)] = pack_bf16(v00, v01);
                    g_candb[sw_pair(bx, r0 + 8, qp)] = pack_bf16(v10, v11);
                } else if (wm == 0 && mi < 2) {      // rows 0..31 valid
                    int d0 = r0, d1 = r0 + 8;
                    int i0 = ((d0 >> 4) * C_ + 2 + (d0 & 15)) * E_ + col0;
                    int i1 = ((d1 >> 4) * C_ + 2 + (d1 & 15)) * E_ + col0;
                    g_xkey[i0] = v00; g_xkey[i0 + 1] = v01;
                    g_xkey[i1] = v10; g_xkey[i1 + 1] = v11;
                }
            }
}

// ---------------------------------------------------------------------------
// k_conv: embed conversion + cand rows + static keys + detect. NO static
// smem -> conversion blocks run at full occupancy.
// ---------------------------------------------------------------------------
__global__ void __launch_bounds__(256) k_conv(const float* __restrict__ z,
                                              const float* __restrict__ y,
                                              const float* __restrict__ Wst,
                                              const int* __restrict__ yt32,
                                              const float* __restrict__ embed) {
    int bx = blockIdx.x, tid = threadIdx.x;
    if (bx < NCONV4) {
        // embed fp32 -> bf16 blocked SW128, one 16B unit per thread
        int idx4 = bx * 256 + tid;             // [0, 1,024,000)
        int v = idx4 >> 5;
        int t = idx4 & 31;
        const float4* src = reinterpret_cast<const float4*>(embed + (size_t)v * E_) + t * 2;
        float4 x01 = src[0], x23 = src[1];
        uint4 wv;
        wv.x = pack_bf16(x01.x, x01.y);
        wv.y = pack_bf16(x01.z, x01.w);
        wv.z = pack_bf16(x23.x, x23.y);
        wv.w = pack_bf16(x23.z, x23.w);
        size_t bb = sw_unit(v >> 7, v & 127, t * 4);
        *reinterpret_cast<uint4*>(reinterpret_cast<char*>(g_ebf) + bb) = wv;
    } else if (bx < NCONV4 + NCAND) {
        // candidate rows 256..639: fp32 + bf16 swizzled
        int idx4 = (bx - NCONV4) * 256 + tid;
        int row = 256 + (idx4 >> 5);
        int t = idx4 & 31;
        float4 a, b2;
        if (row < 512) {
            const float4* s = reinterpret_cast<const float4*>(z + (size_t)(row - 256) * E_) + t * 2;
            a = s[0]; b2 = s[1];
        } else if (row < 544) {
            const float4* s = reinterpret_cast<const float4*>(y + (size_t)(row - 512) * E_) + t * 2;
            a = s[0]; b2 = s[1];
        } else {
            a = make_float4(0.f, 0.f, 0.f, 0.f); b2 = a;
        }
        float4* dst = reinterpret_cast<float4*>(g_cand + (size_t)row * E_) + t * 2;
        dst[0] = a; dst[1] = b2;
        uint4 wv;
        wv.x = pack_bf16(a.x, a.y);
        wv.y = pack_bf16(a.z, a.w);
        wv.z = pack_bf16(b2.x, b2.y);
        wv.w = pack_bf16(b2.z, b2.w);
        size_t bb = sw_unit(row >> 7, row & 127, t * 4);
        *reinterpret_cast<uint4*>(reinterpret_cast<char*>(g_candb) + bb) = wv;
    } else if (bx == NCONV4 + NCAND) {
        g_xkey[tid] = Wst[tid];
        g_xkey[256 + tid] = Wst[256 + tid];
        g_xkey[C_ * E_ + tid] = Wst[tid];
        g_xkey[C_ * E_ + 256 + tid] = Wst[256 + tid];
    } else {
        __shared__ int ok;
        if (tid == 0) { ok = 1; g_blkdone = 0; }
        __syncthreads();
        if (tid < 128 && yt32[2 * tid + 1] != 0) atomicExch(&ok, 0);
        __syncthreads();
        if (tid == 0) g_yt64 = ok;
    }
}

// ---------------------------------------------------------------------------
// Main GEMM+exp-sum kernel (R11 champion shape, unchanged). Grid (5, 125).
// ---------------------------------------------------------------------------
__global__ void __launch_bounds__(256, 1) k_main() {
    extern __shared__ __align__(16) char smem_raw[];
    uint32_t sb = smem_u32(smem_raw);
    uint32_t ab = (sb + 1023u) & ~1023u;
    uint32_t mb = ab;                        // A barrier @+0, chunk barriers @+8..+32
    uint32_t Abase = ab + 1024u;
    uint32_t B0 = Abase + TILE_BYTES;
    uint32_t B1 = B0 + TILE_BYTES;
    float* pssf = reinterpret_cast<float*>(smem_raw + ((B1 + TILE_BYTES) - sb)); // [2][128][4]

    const int tid = threadIdx.x;
    const int lane = tid & 31, wid = tid >> 5;
    const int wm = wid & 1, wn = wid >> 1;
    const int mt = blockIdx.x;               // 0..4
    const int vt0 = blockIdx.y * 2;          // 0..248

    if (tid == 0)
        for (int s = 0; s < 5; ++s) MBARRIER_INIT(mb + 8 * s, 1);
    __syncthreads();
    if (tid == 0) {
        const char* asrc = reinterpret_cast<const char*>(g_candb) + (size_t)mt * TILE_BYTES;
        MBARRIER_EXPECT_TX(mb, TILE_BYTES);
        CP_ASYNC_BULK(Abase, asrc, TILE_BYTES, mb);
        const char* b0src = reinterpret_cast<const char*>(g_ebf) + (size_t)vt0 * TILE_BYTES;
#pragma unroll
        for (int s = 0; s < 4; ++s) {
            MBARRIER_EXPECT_TX(mb + 8 + 8 * s, 2 * CHUNK_BYTES);
            CP_ASYNC_BULK(B0 + s * CHUNK_BYTES, b0src + s * CHUNK_BYTES, CHUNK_BYTES, mb + 8 + 8 * s);
            CP_ASYNC_BULK(B1 + s * CHUNK_BYTES, b0src + TILE_BYTES + s * CHUNK_BYTES, CHUNK_BYTES, mb + 8 + 8 * s);
        }
    }

    // ldmatrix lane address parameters
    const int q = lane >> 3, j = lane & 7;
    const int a_row0 = wm * 64 + ((q & 1) << 3) + j;
    const int a_kd = q >> 1;
    const int b_row0 = wn * 32 + ((q & 2) << 2) + j;
    const int b_kd = q & 1;
    const int g = lane >> 2, t4 = lane & 3;

    float c[2][4][4][4];
#pragma unroll
    for (int h = 0; h < 2; ++h)
#pragma unroll
        for (int mi = 0; mi < 4; ++mi)
#pragma unroll
            for (int nj = 0; nj < 4; ++nj)
#pragma unroll
                for (int e = 0; e < 4; ++e) c[h][mi][nj][e] = 0.f;

    uint32_t afr[2][4][4], bf0[2][2][4], bf1[2][2][4];

    MBARRIER_WAIT(mb, 0);                    // A resident
    MBARRIER_WAIT(mb + 8, 0);                // chunk 0 resident
    load_frags(Abase, B0, B1, 0, a_row0, a_kd, b_row0, b_kd,
               afr[0], bf0[0], bf1[0]);

#pragma unroll
    for (int s = 0; s < 16; ++s) {
        const int cur = s & 1, nxt = cur ^ 1;
        if (s < 15) {
            if (((s + 1) & 3) == 0) MBARRIER_WAIT(mb + 8 + 8 * ((s + 1) >> 2), 0);
            load_frags(Abase, B0, B1, s + 1, a_row0, a_kd, b_row0, b_kd,
                       afr[nxt], bf0[nxt], bf1[nxt]);
        }
#pragma unroll
        for (int mi = 0; mi < 4; ++mi)
#pragma unroll
            for (int p = 0; p < 2; ++p) {
                MMA_BF16(c[0][mi][2 * p],     afr[cur][mi], bf0[cur][p][0], bf0[cur][p][1]);
                MMA_BF16(c[0][mi][2 * p + 1], afr[cur][mi], bf0[cur][p][2], bf0[cur][p][3]);
                MMA_BF16(c[1][mi][2 * p],     afr[cur][mi], bf1[cur][p][0], bf1[cur][p][1]);
                MMA_BF16(c[1][mi][2 * p + 1], afr[cur][mi], bf1[cur][p][2], bf1[cur][p][3]);
            }
    }

    // Epilogue: per-row sum of exp(logit) for both halves
#pragma unroll
    for (int h = 0; h < 2; ++h)
#pragma unroll
        for (int mi = 0; mi < 4; ++mi) {
            float sA = 0.f, sB = 0.f;
#pragma unroll
            for (int nj = 0; nj < 4; ++nj) {
                sA += __expf(c[h][mi][nj][0]) + __expf(c[h][mi][nj][1]);
                sB += __expf(c[h][mi][nj][2]) + __expf(c[h][mi][nj][3]);
            }
            sA += __shfl_xor_sync(0xffffffffu, sA, 1);
            sA += __shfl_xor_sync(0xffffffffu, sA, 2);
            sB += __shfl_xor_sync(0xffffffffu, sB, 1);
            sB += __shfl_xor_sync(0xffffffffu, sB, 2);
            if (t4 == 0) {
                int row = wm * 64 + mi * 16 + g;
                pssf[h * 512 + row * 4 + wn] = sA;
                pssf[h * 512 + (row + 8) * 4 + wn] = sB;
            }
        }
    __syncthreads();
    {
        int h = tid >> 7, row = tid & 127;
        const float* p = pssf + h * 512 + row * 4;
        g_partial[(size_t)(mt * BM + row) * NVT_PAD + (vt0 + h)] =
            p[0] + p[1] + p[2] + p[3];
    }
}

// ---------------------------------------------------------------------------
// k_final: inline logZ reduction + warp-per-component dots + parallel LSE
// tail + fused batch means (R11 champion shape, unchanged).
// ---------------------------------------------------------------------------
__global__ void __launch_bounds__(256) k_final(const float* __restrict__ xsa,
                                               const float* __restrict__ embed,
                                               const void* __restrict__ ytv,
                                               float* __restrict__ out) {
    int bl = blockIdx.x;            // 0..255
    int b = bl >> 7;
    int tid = threadIdx.x;
    int lane = tid & 31, w = tid >> 5;

    __shared__ float xrow[E_], erow[E_];
    __shared__ float lZ[C_], red_s[C_], red_t[C_];

    long long t;
    if (g_yt64) t = ((const long long*)ytv)[bl];
    else        t = (long long)((const int*)ytv)[bl];
    xrow[tid] = xsa[(size_t)bl * E_ + tid];
    erow[tid] = embed[(size_t)t * E_ + tid];

    // Inline reduceZ: logZ for this block's 18 candidate rows.
#pragma unroll
    for (int c = w; c < C_; c += 8) {
        int row = (c == 0) ? bl : (c == 1) ? (256 + bl) : (512 + b * LY_ + (c - 2));
        float v = 0.f;
        for (int i = lane; i < NVT; i += 32) v += g_partial[(size_t)row * NVT_PAD + i];
#pragma unroll
        for (int o = 16; o > 0; o >>= 1) v += __shfl_xor_sync(0xffffffffu, v, o);
        if (lane == 0) lZ[c] = logf(v);
    }
    __syncthreads();

    float4 xa = reinterpret_cast<const float4*>(xrow)[lane * 2];
    float4 xb = reinterpret_cast<const float4*>(xrow)[lane * 2 + 1];
    float4 ea = reinterpret_cast<const float4*>(erow)[lane * 2];
    float4 eb = reinterpret_cast<const float4*>(erow)[lane * 2 + 1];

#pragma unroll
    for (int c = w; c < C_; c += 8) {
        const float4* kr = reinterpret_cast<const float4*>(g_xkey + (size_t)(b * C_ + c) * E_);
        float4 k0 = kr[lane * 2], k1 = kr[lane * 2 + 1];
        float sv = xa.x * k0.x + xa.y * k0.y + xa.z * k0.z + xa.w * k0.w
                 + xb.x * k1.x + xb.y * k1.y + xb.z * k1.z + xb.w * k1.w;

        int crow = (c == 0) ? bl : (c == 1) ? (256 + bl) : (512 + b * LY_ + (c - 2));
        const float4* cr = reinterpret_cast<const float4*>(g_cand + (size_t)crow * E_);
        float4 c0 = cr[lane * 2], c1 = cr[lane * 2 + 1];
        float tv = ea.x * c0.x + ea.y * c0.y + ea.z * c0.z + ea.w * c0.w
                 + eb.x * c1.x + eb.y * c1.y + eb.z * c1.z + eb.w * c1.w;
#pragma unroll
        for (int o = 16; o > 0; o >>= 1) {
            sv += __shfl_xor_sync(0xffffffffu, sv, o);
            tv += __shfl_xor_sync(0xffffffffu, tv, o);
        }
        if (lane == 0) { red_s[c] = sv; red_t[c] = tv; }
    }
    __syncthreads();

    if (tid < 32) {
        bool act = tid < C_;
        float s = act ? red_s[tid] : -1e30f;
        float qv = act ? (s + red_t[tid] - lZ[tid]) : -1e30f;
        float ms = s, mq = qv;
#pragma unroll
        for (int o = 16; o > 0; o >>= 1) {
            ms = fmaxf(ms, __shfl_xor_sync(0xffffffffu, ms, o));
            mq = fmaxf(mq, __shfl_xor_sync(0xffffffffu, mq, o));
        }
        float es = act ? expf(s - ms) : 0.f;
        float eq = act ? expf(qv - mq) : 0.f;
#pragma unroll
        for (int o = 16; o > 0; o >>= 1) {
            es += __shfl_xor_sync(0xffffffffu, es, o);
            eq += __shfl_xor_sync(0xffffffffu, eq, o);
        }
        int done = 0;
        if (tid == 0) {
            g_negcent[bl] = -((mq + logf(eq)) - (ms + logf(es)));
            __threadfence();
            done = atomicAdd(&g_blkdone, 1);
        }
        done = __shfl_sync(0xffffffffu, done, 0);
        if (done == B_ * L_ - 1) {
            float s8 = 0.f;
#pragma unroll
            for (int u = 0; u < 8; ++u) s8 += __ldcg(&g_negcent[tid * 8 + u]);
#pragma unroll
            for (int o = 1; o < 16; o <<= 1) s8 += __shfl_xor_sync(0xffffffffu, s8, o);
            if (tid == 0)  out[0] = s8 / (float)L_;
            if (tid == 16) out[1] = s8 / (float)L_;
        }
    }
}

// ---------------------------------------------------------------------------
extern "C" void kernel_launch(void* const* d_in, const int* in_sizes, int n_in,
                              void* d_out, int out_size) {
    const float* xsa   = (const float*)d_in[0];
    const float* z     = (const float*)d_in[1];
    const float* y     = (const float*)d_in[2];
    const void*  yt    = d_in[3];
    const float* embed = (const float*)d_in[4];
    const float* Wst   = (const float*)d_in[5];
    const float* Wdyn  = (const float*)d_in[6];
    const float* bdyn  = (const float*)d_in[7];
    const float* Wemit = (const float*)d_in[8];
    const float* bemit = (const float*)d_in[9];
    float* out = (float*)d_out;

    cudaFuncSetAttribute(k_main, cudaFuncAttributeMaxDynamicSharedMemorySize,
                         SMEM_REQ);
    cudaFuncSetAttribute(k_sgemm, cudaFuncAttributeMaxDynamicSharedMemorySize,
                         SG_SMEM);

    k_sgemm<<<3, 256, SG_SMEM>>>(xsa, y, Wemit, Wdyn, bemit, bdyn);
    k_conv<<<CONV_BLOCKS, 256>>>(z, y, Wst, (const int*)yt, embed);
    k_main<<<dim3(NMT, NVT / 2), 256, SMEM_REQ>>>();
    k_final<<<B_ * L_, 256>>>(xsa, embed, yt, out);
}

// round 16
// speedup vs baseline: 1.0264x; 1.0264x over previous
#include <cuda_runtime.h>
#include <cuda_bf16.h>
#include <math.h>
#include <stdint.h>

// ---------------- problem constants ----------------
#define B_   2
#define L_   128
#define LY_  16
#define E_   256
#define V_   32000
#define C_   18        // 2 static + LY dynamic mixture components

// Distinct candidate rows: 0..255 emit(b,l), 256..511 z(b,l), 512..543 y(b,j)
#define R_      544
#define RPAD    640    // 5 tiles of 128
#define BM      128
#define NMT     5      // RPAD/BM
#define NVT     250    // V_/128
#define NVT_PAD 256

#define TILE_BYTES  65536     // one 128-row x 256-k bf16 tile (blocked SW128)
#define CHUNK_BYTES 16384     // one k64 chunk (128 rows x 128B)
// k_main: 1023 slack + 1024 ctrl + A + B0 + B1 + pss(4K)
#define SMEM_REQ    202752
// k_prep: 1023 slack + Achunk(16K) + B0chunk(16K) + B1chunk(16K)
#define PREP_SMEM   50176

// k_prep block layout: sgemm first, then conversion / cand / misc
#define NSG2   3              // tensor smallgemm blocks
#define NCONV  4000           // embed conversion blocks (1 unit/thread)
#define NCAND  48             // cand rows 256..639 copy blocks
#define PREP_BLOCKS (NSG2 + NCONV + NCAND + 2)

// ---------------- device scratch (no allocation allowed) ----------------
__device__ float    g_cand[RPAD * E_];
__device__ float    g_xkey[B_ * C_ * E_];
__device__ float    g_partial[RPAD * NVT_PAD];
__device__ float    g_negcent[B_ * L_];
__device__ int      g_yt64;
__device__ int      g_blkdone;                              // k_final finish counter
__device__ uint32_t g_candb[NMT * TILE_BYTES / 4];          // cand bf16, swizzled
__device__ uint32_t g_ebf[(size_t)NVT * TILE_BYTES / 4];    // embed bf16, swizzled

// ---------------- PTX helpers (plain sm_100-safe) ----------
__device__ __forceinline__ uint32_t smem_u32(const void* p) {
    uint32_t a;
    asm("{ .reg .u64 t; cvta.to.shared.u64 t, %1; cvt.u32.u64 %0, t; }"
        : "=r"(a) : "l"(p));
    return a;
}
#define MBARRIER_INIT(mb, cnt) \
    asm volatile("mbarrier.init.shared.b64 [%0], %1;" :: "r"(mb), "r"((uint32_t)(cnt)) : "memory")
#define MBARRIER_EXPECT_TX(mb, bytes) \
    asm volatile("mbarrier.arrive.expect_tx.shared.b64 _, [%0], %1;" \
                 :: "r"(mb), "r"((uint32_t)(bytes)) : "memory")
#define MBARRIER_WAIT(mb, ph) do {                                              \
    uint32_t _mb = (mb), _ph = (ph), _done;                                     \
    asm volatile("{\n\t.reg .pred p;\n\t"                                       \
        "mbarrier.try_wait.parity.acquire.cta.shared::cta.b64 p, [%1], %2;\n\t" \
        "selp.b32 %0, 1, 0, p;\n\t}" : "=r"(_done) : "r"(_mb), "r"(_ph) : "memory"); \
    if (!_done) {                                                               \
        asm volatile("{\n\t.reg .pred P1;\n\t"                                  \
            "WL_%=:\n\t"                                                        \
            "mbarrier.try_wait.parity.acquire.cta.shared::cta.b64 P1, [%0], %1, 0x989680;\n\t" \
            "@P1 bra.uni WD_%=;\n\t"                                            \
            "bra.uni WL_%=;\n\t"                                                \
            "WD_%=:\n\t}" :: "r"(_mb), "r"(_ph) : "memory");                    \
    }                                                                           \
} while (0)
#define CP_ASYNC_BULK(dst, src, bytes, mb) \
    asm volatile("cp.async.bulk.shared::cluster.global.mbarrier::complete_tx::bytes " \
                 "[%0], [%1], %2, [%3];" \
                 :: "r"(dst), "l"(src), "r"((uint32_t)(bytes)), "r"(mb) : "memory")

#define LDSM_X4(r, addr) \
    asm volatile("ldmatrix.sync.aligned.m8n8.x4.shared.b16 {%0,%1,%2,%3}, [%4];" \
        : "=r"((r)[0]), "=r"((r)[1]), "=r"((r)[2]), "=r"((r)[3]) : "r"(addr))

#define MMA_BF16(c, a, b0, b1) \
    asm volatile("mma.sync.aligned.m16n8k16.row.col.f32.bf16.bf16.f32 " \
        "{%0,%1,%2,%3}, {%4,%5,%6,%7}, {%8,%9}, {%0,%1,%2,%3};" \
        : "+f"((c)[0]), "+f"((c)[1]), "+f"((c)[2]), "+f"((c)[3]) \
        : "r"((a)[0]), "r"((a)[1]), "r"((a)[2]), "r"((a)[3]), "r"(b0), "r"(b1))

// pack two fp32 -> bf16x2 word (lo = element k, hi = element k+1), 1 instr
#define CVTPACK(d, lo, hi) \
    asm("cvt.rn.bf16x2.f32 %0, %1, %2;" : "=r"(d) : "f"(hi), "f"(lo))

__device__ __forceinline__ uint32_t pack_bf16(float a, float b) {
    __nv_bfloat162 t(__float2bfloat16_rn(a), __float2bfloat16_rn(b));
    return *reinterpret_cast<uint32_t*>(&t);
}
// swizzled byte offset of the 16B unit holding pairs [q0, q0+4), q0 % 4 == 0
__device__ __forceinline__ size_t sw_unit(int tile, int r, int q0) {
    int c = q0 >> 5;
    int boff = r * 128 + 4 * (q0 & 31);
    int sw = boff ^ ((boff >> 3) & 0x70);
    return (size_t)tile * TILE_BYTES + (size_t)c * CHUNK_BYTES + sw;
}
// swizzled 4B-word index of pair q
__device__ __forceinline__ size_t sw_pair(int tile, int r, int q) {
    int c = q >> 5;
    int boff = r * 128 + 4 * (q & 31);
    int sw = boff ^ ((boff >> 3) & 0x70);
    return ((size_t)tile * TILE_BYTES + (size_t)c * CHUNK_BYTES + sw) >> 2;
}

// Fragment loader for one k16 step (software pipeline unit)
__device__ __forceinline__ void load_frags(
    uint32_t Abase, uint32_t B0, uint32_t B1, int s,
    int a_row0, int a_kd, int b_row0, int b_kd,
    uint32_t (&a)[4][4], uint32_t (&f0)[2][4], uint32_t (&f1)[2][4]) {
    const uint32_t Ac = Abase + (s >> 2) * CHUNK_BYTES;
    const uint32_t Bc0 = B0 + (s >> 2) * CHUNK_BYTES;
    const uint32_t Bc1 = B1 + (s >> 2) * CHUNK_BYTES;
    const int kg = (s & 3) * 2;
#pragma unroll
    for (int mi = 0; mi < 4; ++mi) {
        int r = a_row0 + mi * 16;
        LDSM_X4(a[mi], Ac + r * 128 + (((kg + a_kd) ^ (r & 7)) << 4));
    }
#pragma unroll
    for (int p = 0; p < 2; ++p) {
        int r = b_row0 + p * 16;
        uint32_t off = r * 128 + (((kg + b_kd) ^ (r & 7)) << 4);
        LDSM_X4(f0[p], Bc0 + off);
        LDSM_X4(f1[p], Bc1 + off);
    }
}

// convert one 128x64 fp32 chunk (rowsrc + k window) -> SW128 bf16 chunk @dst
__device__ __forceinline__ void conv_chunk(const float* __restrict__ src,
                                           size_t row_stride, int kofs,
                                           char* dst, int tid, int rclamp) {
    int r = tid >> 1;
    int tb = (tid & 1) * 4;
    int rs = (rclamp > 0) ? (r & (rclamp - 1)) : r;
    const float4* av = reinterpret_cast<const float4*>(src + rs * row_stride + kofs);
#pragma unroll
    for (int i = 0; i < 4; ++i) {
        int t = tb + i;
        float4 a = av[2 * t], b2 = av[2 * t + 1];
        uint4 w;
        CVTPACK(w.x, a.x, a.y);
        CVTPACK(w.y, a.z, a.w);
        CVTPACK(w.z, b2.x, b2.y);
        CVTPACK(w.w, b2.z, b2.w);
        int off = r * 128 + (((t ^ (r & 7))) << 4);
        *reinterpret_cast<uint4*>(dst + off) = w;
    }
}

// ---------------------------------------------------------------------------
// k_prep — ONE kernel, everything overlapped. 50 KB dyn smem (4 blocks/SM).
//   bx 0/1: emit tile bx = xsa[bx*128..] @ Wemit^T + bemit  (tensor cores,
//           K streamed in 4 chunks of 64)
//   bx 2  : dyn keys = y @ Wdyn^T + bdyn
//   bx 3..: embed conversion (1 unit/thread), cand rows, keys, detect
// ---------------------------------------------------------------------------
__global__ void __launch_bounds__(256) k_prep(const float* __restrict__ z,
                                              const float* __restrict__ y,
                                              const float* __restrict__ Wst,
                                              const float* __restrict__ Wemit,
                                              const float* __restrict__ Wdyn,
                                              const int* __restrict__ yt32,
                                              const float* __restrict__ embed,
                                              const float* __restrict__ xsa,
                                              const float* __restrict__ bemit,
                                              const float* __restrict__ bdyn) {
    extern __shared__ __align__(16) char smem_raw[];
    int bx = blockIdx.x, tid = threadIdx.x;

    if (bx < NSG2) {
        uint32_t sb = smem_u32(smem_raw);
        uint32_t ab = (sb + 1023u) & ~1023u;
        uint32_t Abase = ab;
        uint32_t B0 = Abase + CHUNK_BYTES;
        uint32_t B1 = B0 + CHUNK_BYTES;
        char* aptr = smem_raw + (Abase - sb);
        char* b0ptr = smem_raw + (B0 - sb);
        char* b1ptr = smem_raw + (B1 - sb);

        const int lane = tid & 31, wid = tid >> 5;
        const int wm = wid & 1, wn = wid >> 1;
        const float* Asrc = (bx < 2) ? (xsa + (size_t)bx * 128 * E_) : y;
        const float* Bsrc = (bx < 2) ? Wemit : Wdyn;
        const float* bias = (bx < 2) ? bemit : bdyn;
        const int rclamp = (bx == 2) ? 32 : 0;

        const int q = lane >> 3, j = lane & 7;
        const int a_row0 = wm * 64 + ((q & 1) << 3) + j;
        const int a_kd = q >> 1;
        const int b_row0 = wn * 32 + ((q & 2) << 2) + j;
        const int b_kd = q & 1;
        const int g = lane >> 2, t4 = lane & 3;

        float c[2][4][4][4];
#pragma unroll
        for (int h = 0; h < 2; ++h)
#pragma unroll
            for (int mi = 0; mi < 4; ++mi)
#pragma unroll
                for (int nj = 0; nj < 4; ++nj)
#pragma unroll
                    for (int e = 0; e < 4; ++e) c[h][mi][nj][e] = 0.f;

        for (int kc = 0; kc < 4; ++kc) {
            conv_chunk(Asrc, E_, kc * 64, aptr, tid, rclamp);
            conv_chunk(Bsrc, E_, kc * 64, b0ptr, tid, 0);
            conv_chunk(Bsrc + (size_t)128 * E_, E_, kc * 64, b1ptr, tid, 0);
            __syncthreads();

            uint32_t afr[2][4][4], bf0[2][2][4], bf1[2][2][4];
            load_frags(Abase, B0, B1, 0, a_row0, a_kd, b_row0, b_kd,
                       afr[0], bf0[0], bf1[0]);
#pragma unroll
            for (int s = 0; s < 4; ++s) {
                const int cur = s & 1, nxt = cur ^ 1;
                if (s < 3)
                    load_frags(Abase, B0, B1, s + 1, a_row0, a_kd, b_row0, b_kd,
                               afr[nxt], bf0[nxt], bf1[nxt]);
#pragma unroll
                for (int mi = 0; mi < 4; ++mi)
#pragma unroll
                    for (int p = 0; p < 2; ++p) {
                        MMA_BF16(c[0][mi][2 * p],     afr[cur][mi], bf0[cur][p][0], bf0[cur][p][1]);
                        MMA_BF16(c[0][mi][2 * p + 1], afr[cur][mi], bf0[cur][p][2], bf0[cur][p][3]);
                        MMA_BF16(c[1][mi][2 * p],     afr[cur][mi], bf1[cur][p][0], bf1[cur][p][1]);
                        MMA_BF16(c[1][mi][2 * p + 1], afr[cur][mi], bf1[cur][p][2], bf1[cur][p][3]);
                    }
            }
            __syncthreads();
        }

        // Epilogue: bias add + fp32 store (+ bf16 swizzled for emit tiles)
#pragma unroll
        for (int h = 0; h < 2; ++h)
#pragma unroll
            for (int mi = 0; mi < 4; ++mi)
#pragma unroll
                for (int nj = 0; nj < 4; ++nj) {
                    int col0 = h * 128 + wn * 32 + nj * 8 + 2 * t4;
                    float b0v = bias[col0], b1v = bias[col0 + 1];
                    float v00 = c[h][mi][nj][0] + b0v;
                    float v01 = c[h][mi][nj][1] + b1v;
                    float v10 = c[h][mi][nj][2] + b0v;
                    float v11 = c[h][mi][nj][3] + b1v;
                    int r0 = wm * 64 + mi * 16 + g;
                    if (bx < 2) {
                        int row0 = bx * 128 + r0;
                        g_cand[(size_t)row0 * E_ + col0] = v00;
                        g_cand[(size_t)row0 * E_ + col0 + 1] = v01;
                        g_cand[(size_t)(row0 + 8) * E_ + col0] = v10;
                        g_cand[(size_t)(row0 + 8) * E_ + col0 + 1] = v11;
                        int qp = col0 >> 1;
                        g_candb[sw_pair(bx, r0, qp)] = pack_bf16(v00, v01);
                        g_candb[sw_pair(bx, r0 + 8, qp)] = pack_bf16(v10, v11);
                    } else if (wm == 0 && mi < 2) {      // rows 0..31 valid
                        int d0 = r0, d1 = r0 + 8;
                        int i0 = ((d0 >> 4) * C_ + 2 + (d0 & 15)) * E_ + col0;
                        int i1 = ((d1 >> 4) * C_ + 2 + (d1 & 15)) * E_ + col0;
                        g_xkey[i0] = v00; g_xkey[i0 + 1] = v01;
                        g_xkey[i1] = v10; g_xkey[i1 + 1] = v11;
                    }
                }
        return;
    }

    int b = bx - NSG2;
    if (b < NCONV) {
        // embed fp32 -> bf16 blocked SW128, one 16B unit per thread
        int idx4 = b * 256 + tid;              // [0, 1,024,000)
        int v = idx4 >> 5;
        int t = idx4 & 31;
        const float4* src = reinterpret_cast<const float4*>(embed + (size_t)v * E_) + t * 2;
        float4 x01 = src[0], x23 = src[1];
        uint4 wv;
        wv.x = pack_bf16(x01.x, x01.y);
        wv.y = pack_bf16(x01.z, x01.w);
        wv.z = pack_bf16(x23.x, x23.y);
        wv.w = pack_bf16(x23.z, x23.w);
        size_t bb = sw_unit(v >> 7, v & 127, t * 4);
        *reinterpret_cast<uint4*>(reinterpret_cast<char*>(g_ebf) + bb) = wv;
    } else if (b < NCONV + NCAND) {
        // candidate rows 256..639: fp32 + bf16 swizzled
        int idx4 = (b - NCONV) * 256 + tid;
        int row = 256 + (idx4 >> 5);
        int t = idx4 & 31;
        float4 a, b2;
        if (row < 512) {
            const float4* s = reinterpret_cast<const float4*>(z + (size_t)(row - 256) * E_) + t * 2;
            a = s[0]; b2 = s[1];
        } else if (row < 544) {
            const float4* s = reinterpret_cast<const float4*>(y + (size_t)(row - 512) * E_) + t * 2;
            a = s[0]; b2 = s[1];
        } else {
            a = make_float4(0.f, 0.f, 0.f, 0.f); b2 = a;
        }
        float4* dst = reinterpret_cast<float4*>(g_cand + (size_t)row * E_) + t * 2;
        dst[0] = a; dst[1] = b2;
        uint4 wv;
        wv.x = pack_bf16(a.x, a.y);
        wv.y = pack_bf16(a.z, a.w);
        wv.z = pack_bf16(b2.x, b2.y);
        wv.w = pack_bf16(b2.z, b2.w);
        size_t bb = sw_unit(row >> 7, row & 127, t * 4);
        *reinterpret_cast<uint4*>(reinterpret_cast<char*>(g_candb) + bb) = wv;
    } else if (b == NCONV + NCAND) {
        g_xkey[tid] = Wst[tid];
        g_xkey[256 + tid] = Wst[256 + tid];
        g_xkey[C_ * E_ + tid] = Wst[tid];
        g_xkey[C_ * E_ + 256 + tid] = Wst[256 + tid];
    } else {
        __shared__ int ok;
        if (tid == 0) { ok = 1; g_blkdone = 0; }
        __syncthreads();
        if (tid < 128 && yt32[2 * tid + 1] != 0) atomicExch(&ok, 0);
        __syncthreads();
        if (tid == 0) g_yt64 = ok;
    }
}

// ---------------------------------------------------------------------------
// Main GEMM+exp-sum kernel (R11 champion shape, unchanged). Grid (5, 125).
// ---------------------------------------------------------------------------
__global__ void __launch_bounds__(256, 1) k_main() {
    extern __shared__ __align__(16) char smem_raw[];
    uint32_t sb = smem_u32(smem_raw);
    uint32_t ab = (sb + 1023u) & ~1023u;
    uint32_t mb = ab;                        // A barrier @+0, chunk barriers @+8..+32
    uint32_t Abase = ab + 1024u;
    uint32_t B0 = Abase + TILE_BYTES;
    uint32_t B1 = B0 + TILE_BYTES;
    float* pssf = reinterpret_cast<float*>(smem_raw + ((B1 + TILE_BYTES) - sb)); // [2][128][4]

    const int tid = threadIdx.x;
    const int lane = tid & 31, wid = tid >> 5;
    const int wm = wid & 1, wn = wid >> 1;
    const int mt = blockIdx.x;               // 0..4
    const int vt0 = blockIdx.y * 2;          // 0..248

    if (tid == 0)
        for (int s = 0; s < 5; ++s) MBARRIER_INIT(mb + 8 * s, 1);
    __syncthreads();
    if (tid == 0) {
        const char* asrc = reinterpret_cast<const char*>(g_candb) + (size_t)mt * TILE_BYTES;
        MBARRIER_EXPECT_TX(mb, TILE_BYTES);
        CP_ASYNC_BULK(Abase, asrc, TILE_BYTES, mb);
        const char* b0src = reinterpret_cast<const char*>(g_ebf) + (size_t)vt0 * TILE_BYTES;
#pragma unroll
        for (int s = 0; s < 4; ++s) {
            MBARRIER_EXPECT_TX(mb + 8 + 8 * s, 2 * CHUNK_BYTES);
            CP_ASYNC_BULK(B0 + s * CHUNK_BYTES, b0src + s * CHUNK_BYTES, CHUNK_BYTES, mb + 8 + 8 * s);
            CP_ASYNC_BULK(B1 + s * CHUNK_BYTES, b0src + TILE_BYTES + s * CHUNK_BYTES, CHUNK_BYTES, mb + 8 + 8 * s);
        }
    }

    const int q = lane >> 3, j = lane & 7;
    const int a_row0 = wm * 64 + ((q & 1) << 3) + j;
    const int a_kd = q >> 1;
    const int b_row0 = wn * 32 + ((q & 2) << 2) + j;
    const int b_kd = q & 1;
    const int g = lane >> 2, t4 = lane & 3;

    float c[2][4][4][4];
#pragma unroll
    for (int h = 0; h < 2; ++h)
#pragma unroll
        for (int mi = 0; mi < 4; ++mi)
#pragma unroll
            for (int nj = 0; nj < 4; ++nj)
#pragma unroll
                for (int e = 0; e < 4; ++e) c[h][mi][nj][e] = 0.f;

    uint32_t afr[2][4][4], bf0[2][2][4], bf1[2][2][4];

    MBARRIER_WAIT(mb, 0);                    // A resident
    MBARRIER_WAIT(mb + 8, 0);                // chunk 0 resident
    load_frags(Abase, B0, B1, 0, a_row0, a_kd, b_row0, b_kd,
               afr[0], bf0[0], bf1[0]);

#pragma unroll
    for (int s = 0; s < 16; ++s) {
        const int cur = s & 1, nxt = cur ^ 1;
        if (s < 15) {
            if (((s + 1) & 3) == 0) MBARRIER_WAIT(mb + 8 + 8 * ((s + 1) >> 2), 0);
            load_frags(Abase, B0, B1, s + 1, a_row0, a_kd, b_row0, b_kd,
                       afr[nxt], bf0[nxt], bf1[nxt]);
        }
#pragma unroll
        for (int mi = 0; mi < 4; ++mi)
#pragma unroll
            for (int p = 0; p < 2; ++p) {
                MMA_BF16(c[0][mi][2 * p],     afr[cur][mi], bf0[cur][p][0], bf0[cur][p][1]);
                MMA_BF16(c[0][mi][2 * p + 1], afr[cur][mi], bf0[cur][p][2], bf0[cur][p][3]);
                MMA_BF16(c[1][mi][2 * p],     afr[cur][mi], bf1[cur][p][0], bf1[cur][p][1]);
                MMA_BF16(c[1][mi][2 * p + 1], afr[cur][mi], bf1[cur][p][2], bf1[cur][p][3]);
            }
    }

    // Epilogue: per-row sum of exp(logit) for both halves
#pragma unroll
    for (int h = 0; h < 2; ++h)
#pragma unroll
        for (int mi = 0; mi < 4; ++mi) {
            float sA = 0.f, sB = 0.f;
#pragma unroll
            for (int nj = 0; nj < 4; ++nj) {
                sA += __expf(c[h][mi][nj][0]) + __expf(c[h][mi][nj][1]);
                sB += __expf(c[h][mi][nj][2]) + __expf(c[h][mi][nj][3]);
            }
            sA += __shfl_xor_sync(0xffffffffu, sA, 1);
            sA += __shfl_xor_sync(0xffffffffu, sA, 2);
            sB += __shfl_xor_sync(0xffffffffu, sB, 1);
            sB += __shfl_xor_sync(0xffffffffu, sB, 2);
            if (t4 == 0) {
                int row = wm * 64 + mi * 16 + g;
                pssf[h * 512 + row * 4 + wn] = sA;
                pssf[h * 512 + (row + 8) * 4 + wn] = sB;
            }
        }
    __syncthreads();
    {
        int h = tid >> 7, row = tid & 127;
        const float* p = pssf + h * 512 + row * 4;
        g_partial[(size_t)(mt * BM + row) * NVT_PAD + (vt0 + h)] =
            p[0] + p[1] + p[2] + p[3];
    }
}

// ---------------------------------------------------------------------------
// k_final: inline logZ reduction + warp-per-component dots + parallel LSE
// tail + fused batch means (R11 champion shape, unchanged).
// ---------------------------------------------------------------------------
__global__ void __launch_bounds__(256) k_final(const float* __restrict__ xsa,
                                               const float* __restrict__ embed,
                                               const void* __restrict__ ytv,
                                               float* __restrict__ out) {
    int bl = blockIdx.x;            // 0..255
    int b = bl >> 7;
    int tid = threadIdx.x;
    int lane = tid & 31, w = tid >> 5;

    __shared__ float xrow[E_], erow[E_];
    __shared__ float lZ[C_], red_s[C_], red_t[C_];

    long long t;
    if (g_yt64) t = ((const long long*)ytv)[bl];
    else        t = (long long)((const int*)ytv)[bl];
    xrow[tid] = xsa[(size_t)bl * E_ + tid];
    erow[tid] = embed[(size_t)t * E_ + tid];

    // Inline reduceZ: logZ for this block's 18 candidate rows.
#pragma unroll
    for (int c = w; c < C_; c += 8) {
        int row = (c == 0) ? bl : (c == 1) ? (256 + bl) : (512 + b * LY_ + (c - 2));
        float v = 0.f;
        for (int i = lane; i < NVT; i += 32) v += g_partial[(size_t)row * NVT_PAD + i];
#pragma unroll
        for (int o = 16; o > 0; o >>= 1) v += __shfl_xor_sync(0xffffffffu, v, o);
        if (lane == 0) lZ[c] = logf(v);
    }
    __syncthreads();

    float4 xa = reinterpret_cast<const float4*>(xrow)[lane * 2];
    float4 xb = reinterpret_cast<const float4*>(xrow)[lane * 2 + 1];
    float4 ea = reinterpret_cast<const float4*>(erow)[lane * 2];
    float4 eb = reinterpret_cast<const float4*>(erow)[lane * 2 + 1];

#pragma unroll
    for (int c = w; c < C_; c += 8) {
        const float4* kr = reinterpret_cast<const float4*>(g_xkey + (size_t)(b * C_ + c) * E_);
        float4 k0 = kr[lane * 2], k1 = kr[lane * 2 + 1];
        float sv = xa.x * k0.x + xa.y * k0.y + xa.z * k0.z + xa.w * k0.w
                 + xb.x * k1.x + xb.y * k1.y + xb.z * k1.z + xb.w * k1.w;

        int crow = (c == 0) ? bl : (c == 1) ? (256 + bl) : (512 + b * LY_ + (c - 2));
        const float4* cr = reinterpret_cast<const float4*>(g_cand + (size_t)crow * E_);
        float4 c0 = cr[lane * 2], c1 = cr[lane * 2 + 1];
        float tv = ea.x * c0.x + ea.y * c0.y + ea.z * c0.z + ea.w * c0.w
                 + eb.x * c1.x + eb.y * c1.y + eb.z * c1.z + eb.w * c1.w;
#pragma unroll
        for (int o = 16; o > 0; o >>= 1) {
            sv += __shfl_xor_sync(0xffffffffu, sv, o);
            tv += __shfl_xor_sync(0xffffffffu, tv, o);
        }
        if (lane == 0) { red_s[c] = sv; red_t[c] = tv; }
    }
    __syncthreads();

    if (tid < 32) {
        bool act = tid < C_;
        float s = act ? red_s[tid] : -1e30f;
        float qv = act ? (s + red_t[tid] - lZ[tid]) : -1e30f;
        float ms = s, mq = qv;
#pragma unroll
        for (int o = 16; o > 0; o >>= 1) {
            ms = fmaxf(ms, __shfl_xor_sync(0xffffffffu, ms, o));
            mq = fmaxf(mq, __shfl_xor_sync(0xffffffffu, mq, o));
        }
        float es = act ? expf(s - ms) : 0.f;
        float eq = act ? expf(qv - mq) : 0.f;
#pragma unroll
        for (int o = 16; o > 0; o >>= 1) {
            es += __shfl_xor_sync(0xffffffffu, es, o);
            eq += __shfl_xor_sync(0xffffffffu, eq, o);
        }
        int done = 0;
        if (tid == 0) {
            g_negcent[bl] = -((mq + logf(eq)) - (ms + logf(es)));
            __threadfence();
            done = atomicAdd(&g_blkdone, 1);
        }
        done = __shfl_sync(0xffffffffu, done, 0);
        if (done == B_ * L_ - 1) {
            float s8 = 0.f;
#pragma unroll
            for (int u = 0; u < 8; ++u) s8 += __ldcg(&g_negcent[tid * 8 + u]);
#pragma unroll
            for (int o = 1; o < 16; o <<= 1) s8 += __shfl_xor_sync(0xffffffffu, s8, o);
            if (tid == 0)  out[0] = s8 / (float)L_;
            if (tid == 16) out[1] = s8 / (float)L_;
        }
    }
}

// ---------------------------------------------------------------------------
extern "C" void kernel_launch(void* const* d_in, const int* in_sizes, int n_in,
                              void* d_out, int out_size) {
    const float* xsa   = (const float*)d_in[0];
    const float* z     = (const float*)d_in[1];
    const float* y     = (const float*)d_in[2];
    const void*  yt    = d_in[3];
    const float* embed = (const float*)d_in[4];
    const float* Wst   = (const float*)d_in[5];
    const float* Wdyn  = (const float*)d_in[6];
    const float* bdyn  = (const float*)d_in[7];
    const float* Wemit = (const float*)d_in[8];
    const float* bemit = (const float*)d_in[9];
    float* out = (float*)d_out;

    cudaFuncSetAttribute(k_main, cudaFuncAttributeMaxDynamicSharedMemorySize,
                         SMEM_REQ);
    cudaFuncSetAttribute(k_prep, cudaFuncAttributeMaxDynamicSharedMemorySize,
                         PREP_SMEM);

    k_prep<<<PREP_BLOCKS, 256, PREP_SMEM>>>(z, y, Wst, Wemit, Wdyn,
                                            (const int*)yt, embed,
                                            xsa, bemit, bdyn);
    k_main<<<dim3(NMT, NVT / 2), 256, SMEM_REQ>>>();
    k_final<<<B_ * L_, 256>>>(xsa, embed, yt, out);
}

// round 17
// speedup vs baseline: 1.3423x; 1.3077x over previous
#include <cuda_runtime.h>
#include <cuda_bf16.h>
#include <math.h>
#include <stdint.h>

// ---------------- problem constants ----------------
#define B_   2
#define L_   128
#define LY_  16
#define E_   256
#define V_   32000
#define C_   18        // 2 static + LY dynamic mixture components

// Distinct candidate rows: 0..255 emit(b,l), 256..511 z(b,l), 512..543 y(b,j)
#define R_      544
#define RPAD    640    // 5 tiles of 128
#define BM      128
#define NMT     5      // RPAD/BM
#define NVT     250    // V_/128
#define NVT_PAD 256

#define TILE_BYTES  65536     // one 128-row x 256-k bf16 tile (blocked SW128)
#define CHUNK_BYTES 16384     // one k64 chunk (128 rows x 128B)
// 1023 slack + 1024 ctrl + A(64K) + B0(64K) + B1(64K) + pss(4K)
#define SMEM_REQ    202752

// k_prep block layout (R11 shape)
#define NSG    72             // smallgemm blocks (4 rows each)
#define NCONV  4000           // embed conversion blocks (1 unit/thread)
#define NCAND  48             // cand rows 256..639 copy blocks
#define PREP_BLOCKS (NSG + NCONV + NCAND + 2)

// ---------------- device scratch (no allocation allowed) ----------------
__device__ float    g_cand[RPAD * E_];
__device__ float    g_xkey[B_ * C_ * E_];
__device__ float    g_partial[RPAD * NVT_PAD];
__device__ float    g_negcent[B_ * L_];
__device__ int      g_yt64;
__device__ int      g_blkdone;                              // k_final finish counter
__device__ uint32_t g_candb[NMT * TILE_BYTES / 4];          // cand bf16, swizzled
__device__ uint32_t g_ebf[(size_t)NVT * TILE_BYTES / 4];    // embed bf16, swizzled

// ---------------- PTX helpers (plain sm_100-safe) ----------
__device__ __forceinline__ uint32_t smem_u32(const void* p) {
    uint32_t a;
    asm("{ .reg .u64 t; cvta.to.shared.u64 t, %1; cvt.u32.u64 %0, t; }"
        : "=r"(a) : "l"(p));
    return a;
}
#define MBARRIER_INIT(mb, cnt) \
    asm volatile("mbarrier.init.shared.b64 [%0], %1;" :: "r"(mb), "r"((uint32_t)(cnt)) : "memory")
#define MBARRIER_EXPECT_TX(mb, bytes) \
    asm volatile("mbarrier.arrive.expect_tx.shared.b64 _, [%0], %1;" \
                 :: "r"(mb), "r"((uint32_t)(bytes)) : "memory")
#define MBARRIER_WAIT(mb, ph) do {                                              \
    uint32_t _mb = (mb), _ph = (ph), _done;                                     \
    asm volatile("{\n\t.reg .pred p;\n\t"                                       \
        "mbarrier.try_wait.parity.acquire.cta.shared::cta.b64 p, [%1], %2;\n\t" \
        "selp.b32 %0, 1, 0, p;\n\t}" : "=r"(_done) : "r"(_mb), "r"(_ph) : "memory"); \
    if (!_done) {                                                               \
        asm volatile("{\n\t.reg .pred P1;\n\t"                                  \
            "WL_%=:\n\t"                                                        \
            "mbarrier.try_wait.parity.acquire.cta.shared::cta.b64 P1, [%0], %1, 0x989680;\n\t" \
            "@P1 bra.uni WD_%=;\n\t"                                            \
            "bra.uni WL_%=;\n\t"                                                \
            "WD_%=:\n\t}" :: "r"(_mb), "r"(_ph) : "memory");                    \
    }                                                                           \
} while (0)
#define CP_ASYNC_BULK(dst, src, bytes, mb) \
    asm volatile("cp.async.bulk.shared::cluster.global.mbarrier::complete_tx::bytes " \
                 "[%0], [%1], %2, [%3];" \
                 :: "r"(dst), "l"(src), "r"((uint32_t)(bytes)), "r"(mb) : "memory")

#define LDSM_X4(r, addr) \
    asm volatile("ldmatrix.sync.aligned.m8n8.x4.shared.b16 {%0,%1,%2,%3}, [%4];" \
        : "=r"((r)[0]), "=r"((r)[1]), "=r"((r)[2]), "=r"((r)[3]) : "r"(addr))

#define MMA_BF16(c, a, b0, b1) \
    asm volatile("mma.sync.aligned.m16n8k16.row.col.f32.bf16.bf16.f32 " \
        "{%0,%1,%2,%3}, {%4,%5,%6,%7}, {%8,%9}, {%0,%1,%2,%3};" \
        : "+f"((c)[0]), "+f"((c)[1]), "+f"((c)[2]), "+f"((c)[3]) \
        : "r"((a)[0]), "r"((a)[1]), "r"((a)[2]), "r"((a)[3]), "r"(b0), "r"(b1))

__device__ __forceinline__ uint32_t pack_bf16(float a, float b) {
    __nv_bfloat162 t(__float2bfloat16_rn(a), __float2bfloat16_rn(b));
    return *reinterpret_cast<uint32_t*>(&t);
}
// swizzled byte offset of the 16B unit holding pairs [q0, q0+4), q0 % 4 == 0
__device__ __forceinline__ size_t sw_unit(int tile, int r, int q0) {
    int c = q0 >> 5;
    int boff = r * 128 + 4 * (q0 & 31);
    int sw = boff ^ ((boff >> 3) & 0x70);
    return (size_t)tile * TILE_BYTES + (size_t)c * CHUNK_BYTES + sw;
}

// ---------------------------------------------------------------------------
// k_prep — R11 structure; smallgemm W loads now COALESCED via transpose
// staging (warp reads 4 consecutive W rows x 128B; conflict-free smem perm).
// ---------------------------------------------------------------------------
__global__ void __launch_bounds__(256) k_prep(const float* __restrict__ z,
                                              const float* __restrict__ y,
                                              const float* __restrict__ Wst,
                                              const float* __restrict__ Wemit,
                                              const float* __restrict__ Wdyn,
                                              const int* __restrict__ yt32,
                                              const float* __restrict__ embed,
                                              const float* __restrict__ xsa,
                                              const float* __restrict__ bemit,
                                              const float* __restrict__ bdyn) {
    __shared__ float As[4][E_];          // 4 KB
    __shared__ float Wsm[32][257];       // 32.9 KB, [k-within-tile][n]
    int bx = blockIdx.x, tid = threadIdx.x;

    if (bx < NSG) {
        // ---- small GEMM: 4 output rows per block, coalesced W staging ----
        int m0 = bx * 4;
        bool dyn = (m0 >= 256);
        const float* W = dyn ? Wdyn : Wemit;
        const float* Asrc = dyn ? (y + (size_t)(m0 - 256) * E_)
                                : (xsa + (size_t)m0 * E_);
        const float* bias = dyn ? bdyn : bemit;
#pragma unroll
        for (int r = 0; r < 4; ++r) As[r][tid] = Asrc[(size_t)r * E_ + tid];
        float bv = bias[tid];
        float acc[4] = {bv, bv, bv, bv};

        const int lane = tid & 31, wid = tid >> 5;
        const int sub = lane >> 3;           // 0..3  (row within warp quad)
        const int f4 = lane & 7;             // 0..7  (float4 within 128B row seg)

#pragma unroll
        for (int kt = 0; kt < 8; ++kt) {
            __syncthreads();
            // Coalesced load of W[:, kt*32 .. kt*32+32) -> Wsm[k][n]
#pragma unroll
            for (int it = 0; it < 8; ++it) {
                int row = it * 32 + wid * 4 + sub;          // n index 0..255
                float4 wv = *reinterpret_cast<const float4*>(
                    W + (size_t)row * E_ + kt * 32 + f4 * 4);
                Wsm[f4 * 4 + 0][row] = wv.x;
                Wsm[f4 * 4 + 1][row] = wv.y;
                Wsm[f4 * 4 + 2][row] = wv.z;
                Wsm[f4 * 4 + 3][row] = wv.w;
            }
            __syncthreads();
#pragma unroll
            for (int kk = 0; kk < 32; ++kk) {
                float wv = Wsm[kk][tid];
#pragma unroll
                for (int r = 0; r < 4; ++r)
                    acc[r] = fmaf(As[r][kt * 32 + kk], wv, acc[r]);
            }
        }
        if (!dyn) {
#pragma unroll
            for (int r = 0; r < 4; ++r) {
                int row = m0 + r;
                g_cand[(size_t)row * E_ + tid] = acc[r];
                float other = __shfl_xor_sync(0xffffffffu, acc[r], 1);
                if (!(tid & 1)) {
                    int q = tid >> 1;
                    int c = q >> 5;
                    int boff = (row & 127) * 128 + 4 * (q & 31);
                    int sw = boff ^ ((boff >> 3) & 0x70);
                    g_candb[(((size_t)(row >> 7) * TILE_BYTES + (size_t)c * CHUNK_BYTES + sw)) >> 2] =
                        pack_bf16(acc[r], other);
                }
            }
        } else {
#pragma unroll
            for (int r = 0; r < 4; ++r) {
                int d = m0 - 256 + r;
                int bb = d >> 4, j = d & 15;
                g_xkey[(size_t)(bb * C_ + 2 + j) * E_ + tid] = acc[r];
            }
        }
    } else if (bx < NSG + NCONV) {
        // embed fp32 -> bf16 blocked SW128, one 16B unit per thread
        int idx4 = (bx - NSG) * 256 + tid;
        int v = idx4 >> 5;
        int t = idx4 & 31;
        const float4* src = reinterpret_cast<const float4*>(embed + (size_t)v * E_) + t * 2;
        float4 x01 = src[0], x23 = src[1];
        uint4 wv;
        wv.x = pack_bf16(x01.x, x01.y);
        wv.y = pack_bf16(x01.z, x01.w);
        wv.z = pack_bf16(x23.x, x23.y);
        wv.w = pack_bf16(x23.z, x23.w);
        size_t bb = sw_unit(v >> 7, v & 127, t * 4);
        *reinterpret_cast<uint4*>(reinterpret_cast<char*>(g_ebf) + bb) = wv;
    } else if (bx < NSG + NCONV + NCAND) {
        // candidate rows 256..639: fp32 + bf16 swizzled
        int idx4 = (bx - NSG - NCONV) * 256 + tid;
        int row = 256 + (idx4 >> 5);
        int t = idx4 & 31;
        float4 a, b2;
        if (row < 512) {
            const float4* s = reinterpret_cast<const float4*>(z + (size_t)(row - 256) * E_) + t * 2;
            a = s[0]; b2 = s[1];
        } else if (row < 544) {
            const float4* s = reinterpret_cast<const float4*>(y + (size_t)(row - 512) * E_) + t * 2;
            a = s[0]; b2 = s[1];
        } else {
            a = make_float4(0.f, 0.f, 0.f, 0.f); b2 = a;
        }
        float4* dst = reinterpret_cast<float4*>(g_cand + (size_t)row * E_) + t * 2;
        dst[0] = a; dst[1] = b2;
        uint4 wv;
        wv.x = pack_bf16(a.x, a.y);
        wv.y = pack_bf16(a.z, a.w);
        wv.z = pack_bf16(b2.x, b2.y);
        wv.w = pack_bf16(b2.z, b2.w);
        size_t bb = sw_unit(row >> 7, row & 127, t * 4);
        *reinterpret_cast<uint4*>(reinterpret_cast<char*>(g_candb) + bb) = wv;
    } else if (bx == NSG + NCONV + NCAND) {
        g_xkey[tid] = Wst[tid];
        g_xkey[256 + tid] = Wst[256 + tid];
        g_xkey[C_ * E_ + tid] = Wst[tid];
        g_xkey[C_ * E_ + 256 + tid] = Wst[256 + tid];
    } else {
        __shared__ int ok;
        if (tid == 0) { ok = 1; g_blkdone = 0; }
        __syncthreads();
        if (tid < 128 && yt32[2 * tid + 1] != 0) atomicExch(&ok, 0);
        __syncthreads();
        if (tid == 0) g_yt64 = ok;
    }
}

// Fragment loader for one k16 step (software pipeline unit)
__device__ __forceinline__ void load_frags(
    uint32_t Abase, uint32_t B0, uint32_t B1, int s,
    int a_row0, int a_kd, int b_row0, int b_kd,
    uint32_t (&a)[4][4], uint32_t (&f0)[2][4], uint32_t (&f1)[2][4]) {
    const uint32_t Ac = Abase + (s >> 2) * CHUNK_BYTES;
    const uint32_t Bc0 = B0 + (s >> 2) * CHUNK_BYTES;
    const uint32_t Bc1 = B1 + (s >> 2) * CHUNK_BYTES;
    const int kg = (s & 3) * 2;
#pragma unroll
    for (int mi = 0; mi < 4; ++mi) {
        int r = a_row0 + mi * 16;
        LDSM_X4(a[mi], Ac + r * 128 + (((kg + a_kd) ^ (r & 7)) << 4));
    }
#pragma unroll
    for (int p = 0; p < 2; ++p) {
        int r = b_row0 + p * 16;
        uint32_t off = r * 128 + (((kg + b_kd) ^ (r & 7)) << 4);
        LDSM_X4(f0[p], Bc0 + off);
        LDSM_X4(f1[p], Bc1 + off);
    }
}

// ---------------------------------------------------------------------------
// Main GEMM+exp-sum kernel (R11 champion shape, unchanged). Grid (5, 125).
// ---------------------------------------------------------------------------
__global__ void __launch_bounds__(256, 1) k_main() {
    extern __shared__ __align__(16) char smem_raw[];
    uint32_t sb = smem_u32(smem_raw);
    uint32_t ab = (sb + 1023u) & ~1023u;
    uint32_t mb = ab;                        // A barrier @+0, chunk barriers @+8..+32
    uint32_t Abase = ab + 1024u;
    uint32_t B0 = Abase + TILE_BYTES;
    uint32_t B1 = B0 + TILE_BYTES;
    float* pssf = reinterpret_cast<float*>(smem_raw + ((B1 + TILE_BYTES) - sb)); // [2][128][4]

    const int tid = threadIdx.x;
    const int lane = tid & 31, wid = tid >> 5;
    const int wm = wid & 1, wn = wid >> 1;
    const int mt = blockIdx.x;               // 0..4
    const int vt0 = blockIdx.y * 2;          // 0..248

    if (tid == 0)
        for (int s = 0; s < 5; ++s) MBARRIER_INIT(mb + 8 * s, 1);
    __syncthreads();
    if (tid == 0) {
        const char* asrc = reinterpret_cast<const char*>(g_candb) + (size_t)mt * TILE_BYTES;
        MBARRIER_EXPECT_TX(mb, TILE_BYTES);
        CP_ASYNC_BULK(Abase, asrc, TILE_BYTES, mb);
        const char* b0src = reinterpret_cast<const char*>(g_ebf) + (size_t)vt0 * TILE_BYTES;
#pragma unroll
        for (int s = 0; s < 4; ++s) {
            MBARRIER_EXPECT_TX(mb + 8 + 8 * s, 2 * CHUNK_BYTES);
            CP_ASYNC_BULK(B0 + s * CHUNK_BYTES, b0src + s * CHUNK_BYTES, CHUNK_BYTES, mb + 8 + 8 * s);
            CP_ASYNC_BULK(B1 + s * CHUNK_BYTES, b0src + TILE_BYTES + s * CHUNK_BYTES, CHUNK_BYTES, mb + 8 + 8 * s);
        }
    }

    const int q = lane >> 3, j = lane & 7;
    const int a_row0 = wm * 64 + ((q & 1) << 3) + j;
    const int a_kd = q >> 1;
    const int b_row0 = wn * 32 + ((q & 2) << 2) + j;
    const int b_kd = q & 1;
    const int g = lane >> 2, t4 = lane & 3;

    float c[2][4][4][4];
#pragma unroll
    for (int h = 0; h < 2; ++h)
#pragma unroll
        for (int mi = 0; mi < 4; ++mi)
#pragma unroll
            for (int nj = 0; nj < 4; ++nj)
#pragma unroll
                for (int e = 0; e < 4; ++e) c[h][mi][nj][e] = 0.f;

    uint32_t afr[2][4][4], bf0[2][2][4], bf1[2][2][4];

    MBARRIER_WAIT(mb, 0);                    // A resident
    MBARRIER_WAIT(mb + 8, 0);                // chunk 0 resident
    load_frags(Abase, B0, B1, 0, a_row0, a_kd, b_row0, b_kd,
               afr[0], bf0[0], bf1[0]);

#pragma unroll
    for (int s = 0; s < 16; ++s) {
        const int cur = s & 1, nxt = cur ^ 1;
        if (s < 15) {
            if (((s + 1) & 3) == 0) MBARRIER_WAIT(mb + 8 + 8 * ((s + 1) >> 2), 0);
            load_frags(Abase, B0, B1, s + 1, a_row0, a_kd, b_row0, b_kd,
                       afr[nxt], bf0[nxt], bf1[nxt]);
        }
#pragma unroll
        for (int mi = 0; mi < 4; ++mi)
#pragma unroll
            for (int p = 0; p < 2; ++p) {
                MMA_BF16(c[0][mi][2 * p],     afr[cur][mi], bf0[cur][p][0], bf0[cur][p][1]);
                MMA_BF16(c[0][mi][2 * p + 1], afr[cur][mi], bf0[cur][p][2], bf0[cur][p][3]);
                MMA_BF16(c[1][mi][2 * p],     afr[cur][mi], bf1[cur][p][0], bf1[cur][p][1]);
                MMA_BF16(c[1][mi][2 * p + 1], afr[cur][mi], bf1[cur][p][2], bf1[cur][p][3]);
            }
    }

    // Epilogue: per-row sum of exp(logit) for both halves
#pragma unroll
    for (int h = 0; h < 2; ++h)
#pragma unroll
        for (int mi = 0; mi < 4; ++mi) {
            float sA = 0.f, sB = 0.f;
#pragma unroll
            for (int nj = 0; nj < 4; ++nj) {
                sA += __expf(c[h][mi][nj][0]) + __expf(c[h][mi][nj][1]);
                sB += __expf(c[h][mi][nj][2]) + __expf(c[h][mi][nj][3]);
            }
            sA += __shfl_xor_sync(0xffffffffu, sA, 1);
            sA += __shfl_xor_sync(0xffffffffu, sA, 2);
            sB += __shfl_xor_sync(0xffffffffu, sB, 1);
            sB += __shfl_xor_sync(0xffffffffu, sB, 2);
            if (t4 == 0) {
                int row = wm * 64 + mi * 16 + g;
                pssf[h * 512 + row * 4 + wn] = sA;
                pssf[h * 512 + (row + 8) * 4 + wn] = sB;
            }
        }
    __syncthreads();
    {
        int h = tid >> 7, row = tid & 127;
        const float* p = pssf + h * 512 + row * 4;
        g_partial[(size_t)(mt * BM + row) * NVT_PAD + (vt0 + h)] =
            p[0] + p[1] + p[2] + p[3];
    }
}

// ---------------------------------------------------------------------------
// k_final: inline logZ reduction + warp-per-component dots + parallel LSE
// tail + fused batch means (R11 champion shape, unchanged).
// ---------------------------------------------------------------------------
__global__ void __launch_bounds__(256) k_final(const float* __restrict__ xsa,
                                               const float* __restrict__ embed,
                                               const void* __restrict__ ytv,
                                               float* __restrict__ out) {
    int bl = blockIdx.x;            // 0..255
    int b = bl >> 7;
    int tid = threadIdx.x;
    int lane = tid & 31, w = tid >> 5;

    __shared__ float xrow[E_], erow[E_];
    __shared__ float lZ[C_], red_s[C_], red_t[C_];

    long long t;
    if (g_yt64) t = ((const long long*)ytv)[bl];
    else        t = (long long)((const int*)ytv)[bl];
    xrow[tid] = xsa[(size_t)bl * E_ + tid];
    erow[tid] = embed[(size_t)t * E_ + tid];

    // Inline reduceZ: logZ for this block's 18 candidate rows.
#pragma unroll
    for (int c = w; c < C_; c += 8) {
        int row = (c == 0) ? bl : (c == 1) ? (256 + bl) : (512 + b * LY_ + (c - 2));
        float v = 0.f;
        for (int i = lane; i < NVT; i += 32) v += g_partial[(size_t)row * NVT_PAD + i];
#pragma unroll
        for (int o = 16; o > 0; o >>= 1) v += __shfl_xor_sync(0xffffffffu, v, o);
        if (lane == 0) lZ[c] = logf(v);
    }
    __syncthreads();

    float4 xa = reinterpret_cast<const float4*>(xrow)[lane * 2];
    float4 xb = reinterpret_cast<const float4*>(xrow)[lane * 2 + 1];
    float4 ea = reinterpret_cast<const float4*>(erow)[lane * 2];
    float4 eb = reinterpret_cast<const float4*>(erow)[lane * 2 + 1];

#pragma unroll
    for (int c = w; c < C_; c += 8) {
        const float4* kr = reinterpret_cast<const float4*>(g_xkey + (size_t)(b * C_ + c) * E_);
        float4 k0 = kr[lane * 2], k1 = kr[lane * 2 + 1];
        float sv = xa.x * k0.x + xa.y * k0.y + xa.z * k0.z + xa.w * k0.w
                 + xb.x * k1.x + xb.y * k1.y + xb.z * k1.z + xb.w * k1.w;

        int crow = (c == 0) ? bl : (c == 1) ? (256 + bl) : (512 + b * LY_ + (c - 2));
        const float4* cr = reinterpret_cast<const float4*>(g_cand + (size_t)crow * E_);
        float4 c0 = cr[lane * 2], c1 = cr[lane * 2 + 1];
        float tv = ea.x * c0.x + ea.y * c0.y + ea.z * c0.z + ea.w * c0.w
                 + eb.x * c1.x + eb.y * c1.y + eb.z * c1.z + eb.w * c1.w;
#pragma unroll
        for (int o = 16; o > 0; o >>= 1) {
            sv += __shfl_xor_sync(0xffffffffu, sv, o);
            tv += __shfl_xor_sync(0xffffffffu, tv, o);
        }
        if (lane == 0) { red_s[c] = sv; red_t[c] = tv; }
    }
    __syncthreads();

    if (tid < 32) {
        bool act = tid < C_;
        float s = act ? red_s[tid] : -1e30f;
        float qv = act ? (s + red_t[tid] - lZ[tid]) : -1e30f;
        float ms = s, mq = qv;
#pragma unroll
        for (int o = 16; o > 0; o >>= 1) {
            ms = fmaxf(ms, __shfl_xor_sync(0xffffffffu, ms, o));
            mq = fmaxf(mq, __shfl_xor_sync(0xffffffffu, mq, o));
        }
        float es = act ? expf(s - ms) : 0.f;
        float eq = act ? expf(qv - mq) : 0.f;
#pragma unroll
        for (int o = 16; o > 0; o >>= 1) {
            es += __shfl_xor_sync(0xffffffffu, es, o);
            eq += __shfl_xor_sync(0xffffffffu, eq, o);
        }
        int done = 0;
        if (tid == 0) {
            g_negcent[bl] = -((mq + logf(eq)) - (ms + logf(es)));
            __threadfence();
            done = atomicAdd(&g_blkdone, 1);
        }
        done = __shfl_sync(0xffffffffu, done, 0);
        if (done == B_ * L_ - 1) {
            float s8 = 0.f;
#pragma unroll
            for (int u = 0; u < 8; ++u) s8 += __ldcg(&g_negcent[tid * 8 + u]);
#pragma unroll
            for (int o = 1; o < 16; o <<= 1) s8 += __shfl_xor_sync(0xffffffffu, s8, o);
            if (tid == 0)  out[0] = s8 / (float)L_;
            if (tid == 16) out[1] = s8 / (float)L_;
        }
    }
}

// ---------------------------------------------------------------------------
extern "C" void kernel_launch(void* const* d_in, const int* in_sizes, int n_in,
                              void* d_out, int out_size) {
    const float* xsa   = (const float*)d_in[0];
    const float* z     = (const float*)d_in[1];
    const float* y     = (const float*)d_in[2];
    const void*  yt    = d_in[3];
    const float* embed = (const float*)d_in[4];
    const float* Wst   = (const float*)d_in[5];
    const float* Wdyn  = (const float*)d_in[6];
    const float* bdyn  = (const float*)d_in[7];
    const float* Wemit = (const float*)d_in[8];
    const float* bemit = (const float*)d_in[9];
    float* out = (float*)d_out;

    cudaFuncSetAttribute(k_main, cudaFuncAttributeMaxDynamicSharedMemorySize,
                         SMEM_REQ);

    k_prep<<<PREP_BLOCKS, 256>>>(z, y, Wst, Wemit, Wdyn, (const int*)yt, embed,
                                 xsa, bemit, bdyn);
    k_main<<<dim3(NMT, NVT / 2), 256, SMEM_REQ>>>();
    k_final<<<B_ * L_, 256>>>(xsa, embed, yt, out);
}